// round 1
// baseline (speedup 1.0000x reference)
#include <cuda_runtime.h>
#include <math.h>

#define NFEAT   256
#define HIDDEN  256
#define CG      4
#define PCH     64
#define NCLASS  4
#define MAXN    100000
#define MAXE    1600000

// ---------------- device scratch (no allocations allowed) ----------------
__device__ int   g_is64;
__device__ float g_CW[HIDDEN * NFEAT];     // folded lin∘conv weight: [t][f]
__device__ float g_cb[HIDDEN];             // folded bias
__device__ float g_proj[MAXN * 8];         // per node: proj_a[0..3], proj_b[0..3]
__device__ float g_c[(size_t)MAXN * HIDDEN];

// ---------------- index width sniffing ----------------
// Values are in [0, N) < 2^31. If stored as int64 (little endian), every odd
// 32-bit word of the first few elements is 0. If int32, odd words are real
// indices (vanishingly unlikely to ALL be zero across 64 samples).
__global__ void k_detect(const unsigned int* __restrict__ rowp, int E) {
    if (threadIdx.x == 0 && blockIdx.x == 0) {
        int n = E < 64 ? E : 64;
        int all_hi_zero = 1;
        for (int i = 0; i < n; i++) {
            if (rowp[2 * i + 1] != 0u) { all_hi_zero = 0; break; }
        }
        g_is64 = all_hi_zero;
    }
}

// ---------------- fold conv into lin: CW[t][f] = sum_p conv[k,q,p]*lin[k,p,f]
__global__ void k_fold(const float* __restrict__ conv_W,
                       const float* __restrict__ lin_W,
                       const float* __restrict__ lin_b) {
    int t = blockIdx.x;        // 0..255 -> (k,q)
    int f = threadIdx.x;       // 0..255
    int k = t >> 6;
    int q = t & 63;
    const float* cw = conv_W + (k * PCH + q) * PCH;    // conv_W[k][q][p]
    const float* lw = lin_W + (size_t)k * PCH * NFEAT; // lin_W[k][p][f]
    float s = 0.f;
    #pragma unroll 8
    for (int p = 0; p < PCH; p++) s = fmaf(cw[p], lw[p * NFEAT + f], s);
    g_CW[t * NFEAT + f] = s;
    if (f == 0) {
        const float* lb = lin_b + k * PCH;
        float b = 0.f;
        for (int p = 0; p < PCH; p++) b = fmaf(cw[p], lb[p], b);
        g_cb[t] = b;
    }
}

// ---------------- per-node projections for assignment MLP ----------------
__global__ void k_proj(const float* __restrict__ x,
                       const float* __restrict__ asg_W1, int N) {
    int warp = (blockIdx.x * blockDim.x + threadIdx.x) >> 5;
    int lane = threadIdx.x & 31;
    if (warp >= N) return;
    const float* xr = x + (size_t)warp * NFEAT;
    float pa[4] = {0, 0, 0, 0}, pb[4] = {0, 0, 0, 0};
    #pragma unroll
    for (int t = 0; t < 8; t++) {
        int f = lane + 32 * t;
        float xv = xr[f];
        #pragma unroll
        for (int c = 0; c < 4; c++) {
            pa[c] = fmaf(xv, asg_W1[c * 512 + f], pa[c]);
            pb[c] = fmaf(xv, asg_W1[c * 512 + 256 + f], pb[c]);
        }
    }
    #pragma unroll
    for (int c = 0; c < 4; c++) {
        #pragma unroll
        for (int o = 16; o > 0; o >>= 1) {
            pa[c] += __shfl_xor_sync(0xFFFFFFFFu, pa[c], o);
            pb[c] += __shfl_xor_sync(0xFFFFFFFFu, pb[c], o);
        }
    }
    if (lane == 0) {
        #pragma unroll
        for (int c = 0; c < 4; c++) {
            g_proj[warp * 8 + c]     = pa[c];
            g_proj[warp * 8 + 4 + c] = pb[c];
        }
    }
}

// ---------------- c = X @ CW^T + cb  (128x128 tile, 8x8 micro) ----------------
#define BM 128
#define BN 128
#define BK 8
__global__ __launch_bounds__(256, 2)
void k_cgemm(const float* __restrict__ X, int N) {
    __shared__ float As[BK][BM + 4];
    __shared__ float Bs[BK][BN + 4];
    int m0 = blockIdx.x * BM;
    int n0 = blockIdx.y * BN;
    int tid = threadIdx.x;            // 256
    int ty = tid >> 4, tx = tid & 15; // 16x16
    int lm = tid >> 1;                // 0..127 loader row
    int lf = (tid & 1) * 4;           // 0 or 4

    float acc[8][8];
    #pragma unroll
    for (int i = 0; i < 8; i++)
        #pragma unroll
        for (int j = 0; j < 8; j++) acc[i][j] = 0.f;

    for (int k0 = 0; k0 < NFEAT; k0 += BK) {
        float4 av;
        int gm = m0 + lm;
        if (gm < N) av = *(const float4*)(X + (size_t)gm * NFEAT + k0 + lf);
        else        av = make_float4(0.f, 0.f, 0.f, 0.f);
        As[lf + 0][lm] = av.x; As[lf + 1][lm] = av.y;
        As[lf + 2][lm] = av.z; As[lf + 3][lm] = av.w;

        float4 bv = *(const float4*)(g_CW + (n0 + lm) * NFEAT + k0 + lf);
        Bs[lf + 0][lm] = bv.x; Bs[lf + 1][lm] = bv.y;
        Bs[lf + 2][lm] = bv.z; Bs[lf + 3][lm] = bv.w;
        __syncthreads();

        #pragma unroll
        for (int kk = 0; kk < BK; kk++) {
            float a[8], b[8];
            *(float4*)&a[0] = *(const float4*)&As[kk][ty * 8];
            *(float4*)&a[4] = *(const float4*)&As[kk][ty * 8 + 4];
            *(float4*)&b[0] = *(const float4*)&Bs[kk][tx * 8];
            *(float4*)&b[4] = *(const float4*)&Bs[kk][tx * 8 + 4];
            #pragma unroll
            for (int i = 0; i < 8; i++)
                #pragma unroll
                for (int j = 0; j < 8; j++)
                    acc[i][j] = fmaf(a[i], b[j], acc[i][j]);
        }
        __syncthreads();
    }

    #pragma unroll
    for (int i = 0; i < 8; i++) {
        int gm = m0 + ty * 8 + i;
        if (gm >= N) break;
        float* outp = g_c + (size_t)gm * HIDDEN + n0 + tx * 8;
        #pragma unroll
        for (int j = 0; j < 8; j += 4) {
            float4 v;
            v.x = acc[i][j + 0] + g_cb[n0 + tx * 8 + j + 0];
            v.y = acc[i][j + 1] + g_cb[n0 + tx * 8 + j + 1];
            v.z = acc[i][j + 2] + g_cb[n0 + tx * 8 + j + 2];
            v.w = acc[i][j + 3] + g_cb[n0 + tx * 8 + j + 3];
            *(float4*)(outp + j) = v;
        }
    }
}

// ---------------- init out = bias (broadcast per node) ----------------
__global__ void k_init(float* __restrict__ h, const float* __restrict__ bias,
                       int total) {
    int i = blockIdx.x * blockDim.x + threadIdx.x;
    if (i < total) h[i] = bias[i & (HIDDEN - 1)];
}

// ---------------- edge kernel: softmax weight + scatter-add ----------------
__global__ __launch_bounds__(256)
void k_edge(const void* __restrict__ rowp, const void* __restrict__ colp,
            const float* __restrict__ asg_b1, const float* __restrict__ asg_W2,
            const float* __restrict__ asg_b2, float* __restrict__ hout, int E) {
    __shared__ float s_b1[4], s_W2[16], s_b2[4];
    if (threadIdx.x < 4)  s_b1[threadIdx.x] = asg_b1[threadIdx.x];
    if (threadIdx.x >= 4 && threadIdx.x < 20) s_W2[threadIdx.x - 4] = asg_W2[threadIdx.x - 4];
    if (threadIdx.x >= 20 && threadIdx.x < 24) s_b2[threadIdx.x - 20] = asg_b2[threadIdx.x - 20];
    __syncthreads();

    int e    = (blockIdx.x * blockDim.x + threadIdx.x) >> 5;
    int lane = threadIdx.x & 31;
    if (e >= E) return;

    long long r, c;
    if (g_is64) {
        r = ((const long long*)rowp)[e];
        c = ((const long long*)colp)[e];
    } else {
        r = ((const int*)rowp)[e];
        c = ((const int*)colp)[e];
    }

    // assignment MLP + softmax (redundant across lanes; all loads broadcast)
    float h1[4];
    #pragma unroll
    for (int k = 0; k < 4; k++)
        h1[k] = g_proj[c * 8 + k] + g_proj[r * 8 + 4 + k] + s_b1[k];
    float h2[4];
    float mx = -1e30f;
    #pragma unroll
    for (int k = 0; k < 4; k++) {
        float s = s_b2[k];
        #pragma unroll
        for (int d = 0; d < 4; d++) s = fmaf(h1[d], s_W2[k * 4 + d], s);
        h2[k] = s;
        mx = fmaxf(mx, s);
    }
    float w[4];
    float sum = 0.f;
    #pragma unroll
    for (int k = 0; k < 4; k++) { w[k] = __expf(h2[k] - mx); sum += w[k]; }
    float inv = 1.f / sum;
    #pragma unroll
    for (int k = 0; k < 4; k++) w[k] *= inv;

    const float* cr = g_c + (size_t)c * HIDDEN;
    float* orow = hout + (size_t)r * HIDDEN;
    #pragma unroll
    for (int t = 0; t < 8; t++) {
        int j = lane + 32 * t;
        atomicAdd(orow + j, cr[j] * w[t >> 1]);   // group of j = (lane+32t)>>6 = t>>1
    }
}

// ---------------- per-group L2 normalize + classifier ----------------
__global__ void k_norm_cls(float* __restrict__ hout, float* __restrict__ logits,
                           const float* __restrict__ cls_W,
                           const float* __restrict__ cls_b, int N) {
    int n    = (blockIdx.x * blockDim.x + threadIdx.x) >> 5;
    int lane = threadIdx.x & 31;
    if (n >= N) return;
    float* hr = hout + (size_t)n * HIDDEN;

    float v[8];
    float ss[4] = {0, 0, 0, 0};
    #pragma unroll
    for (int t = 0; t < 8; t++) {
        v[t] = hr[lane + 32 * t];
        ss[t >> 1] = fmaf(v[t], v[t], ss[t >> 1]);
    }
    #pragma unroll
    for (int k = 0; k < 4; k++)
        #pragma unroll
        for (int o = 16; o > 0; o >>= 1)
            ss[k] += __shfl_xor_sync(0xFFFFFFFFu, ss[k], o);

    float invn[4];
    #pragma unroll
    for (int k = 0; k < 4; k++)
        invn[k] = 1.f / fmaxf(sqrtf(ss[k]), 1e-12f);

    float lp[4] = {0, 0, 0, 0};
    #pragma unroll
    for (int t = 0; t < 8; t++) {
        v[t] *= invn[t >> 1];
        int j = lane + 32 * t;
        hr[j] = v[t];
        #pragma unroll
        for (int cc = 0; cc < 4; cc++)
            lp[cc] = fmaf(v[t], cls_W[cc * HIDDEN + j], lp[cc]);
    }
    #pragma unroll
    for (int cc = 0; cc < 4; cc++)
        #pragma unroll
        for (int o = 16; o > 0; o >>= 1)
            lp[cc] += __shfl_xor_sync(0xFFFFFFFFu, lp[cc], o);

    if (lane == 0) {
        #pragma unroll
        for (int cc = 0; cc < 4; cc++)
            logits[(size_t)n * NCLASS + cc] = lp[cc] + cls_b[cc];
    }
}

// ---------------- launch ----------------
extern "C" void kernel_launch(void* const* d_in, const int* in_sizes, int n_in,
                              void* d_out, int out_size) {
    const float* x      = (const float*)d_in[0];
    const void*  rowp   = d_in[1];
    const void*  colp   = d_in[2];
    const float* asg_W1 = (const float*)d_in[3];
    const float* asg_b1 = (const float*)d_in[4];
    const float* asg_W2 = (const float*)d_in[5];
    const float* asg_b2 = (const float*)d_in[6];
    const float* lin_W  = (const float*)d_in[7];
    const float* lin_b  = (const float*)d_in[8];
    const float* conv_W = (const float*)d_in[9];
    const float* bias   = (const float*)d_in[10];
    const float* cls_W  = (const float*)d_in[11];
    const float* cls_b  = (const float*)d_in[12];

    int N = in_sizes[0] / NFEAT;
    int E = in_sizes[1];

    float* hout   = (float*)d_out;
    float* logits = hout + (size_t)N * HIDDEN;

    k_detect<<<1, 32>>>((const unsigned int*)rowp, E);
    k_fold<<<HIDDEN, NFEAT>>>(conv_W, lin_W, lin_b);
    k_proj<<<(N + 7) / 8, 256>>>(x, asg_W1, N);
    dim3 gg((N + BM - 1) / BM, HIDDEN / BN);
    k_cgemm<<<gg, 256>>>(x, N);
    k_init<<<(N * HIDDEN + 255) / 256, 256>>>(hout, bias, N * HIDDEN);
    k_edge<<<(E + 7) / 8, 256>>>(rowp, colp, asg_b1, asg_W2, asg_b2, hout, E);
    k_norm_cls<<<(N + 7) / 8, 256>>>(hout, logits, cls_W, cls_b, N);
}